// round 5
// baseline (speedup 1.0000x reference)
#include <cuda_runtime.h>
#include <cstdint>
#include <math.h>

#define BATCH 32768
#define NA 9
#define NR 4
#define LRS 0.2f
#define BN_EPS 1e-5f
#define MTOT (BATCH*NA)
#define TPB 576

// ---- scratch (device globals; no allocs) ----
__device__ float g_h0[(size_t)MTOT*64];
__device__ float g_h1[(size_t)MTOT*128];
__device__ float g_h2[(size_t)MTOT*256];
__device__ float g_wt[256*640];
__device__ float g_stats[3][2][16];

__global__ void zero_stats_kernel() {
    int i = threadIdx.x;
    if (i < 96) ((float*)g_stats)[i] = 0.0f;
}

// ---------------- helpers ----------------
static __device__ __forceinline__ uint32_t s2u(const void* p){
    uint32_t a;
    asm("{ .reg .u64 t; cvta.to.shared.u64 t, %1; cvt.u32.u64 %0, t; }":"=r"(a):"l"(p));
    return a;
}
static __device__ __forceinline__ float tf32r(float v){
    uint32_t u; asm("cvt.rna.tf32.f32 %0, %1;" : "=r"(u) : "f"(v));
    return __uint_as_float(u);
}
#define CPA16(dst,src) asm volatile("cp.async.cg.shared.global [%0], [%1], 16;"::"r"(dst),"l"(src):"memory")
#define CPA_COMMIT()   asm volatile("cp.async.commit_group;":::"memory")
#define CPA_WAIT(n)    asm volatile("cp.async.wait_group %0;"::"n"(n):"memory")

static __device__ __forceinline__ void mma_tf32(
    float& d0, float& d1, float& d2, float& d3,
    uint32_t a0, uint32_t a1, uint32_t a2, uint32_t a3,
    uint32_t b0, uint32_t b1)
{
    asm volatile(
        "mma.sync.aligned.m16n8k8.row.col.f32.tf32.tf32.f32 "
        "{%0,%1,%2,%3}, {%4,%5,%6,%7}, {%8,%9}, {%0,%1,%2,%3};"
        : "+f"(d0), "+f"(d1), "+f"(d2), "+f"(d3)
        : "r"(a0), "r"(a1), "r"(a2), "r"(a3), "r"(b0), "r"(b1));
}

// ---------------- Wt build: frag-packed, per-mat K padded to KPM, tf32-rounded ----
// For (n, k=mat*KPM+kk): kstep=k/8; off = ((n/8)*(KTOT/8)+kstep)*64 + ((n%8)*4+(k&3))*2 + ((k>>2)&1)
template<int DIN,int DOUT,int KPM>
__global__ void wt_build(const float* __restrict__ ws, const float* __restrict__ wr,
                         float* __restrict__ bp){
    constexpr int KTOT = 5*KPM;
    int i = blockIdx.x*256 + threadIdx.x;
    if (i >= DOUT*KTOT) return;
    int n = i / KTOT, k = i - n*KTOT;
    int mat = k / KPM, kk = k - mat*KPM;
    float v = 0.f;
    if (kk < DIN)
        v = (mat == 0) ? ws[kk*DOUT + n] : wr[(size_t)((mat-1)*DIN + kk)*DOUT + n];
    int kstep = k >> 3;
    int lane = (n & 7)*4 + (k & 3), half = (k >> 2) & 1;
    bp[((size_t)(n >> 3)*(KTOT/8) + kstep)*64 + lane*2 + half] = tf32r(v);
}

// ---------------- fused RGCN block ----------------
// CTA = 16 batches (144 rows). A-tiles produced on the fly from h_s/adj_s.
// 18 warps: MMA warp=(mtile 0..8, nhalf 0..1); produce warps 0..15 = one batch each.
template<int DIN, int KPM, int N, int KC, int SOUT, bool NORM, int SIN>
__global__ void __launch_bounds__(TPB,1) rgcn_fused(
    const float* __restrict__ hin,   // [B,9,DIN] raw prev output (or atom_feats)
    const float* __restrict__ adj,   // [B,4,9,9]
    const float* __restrict__ Bp,    // frag-packed weights
    const float* __restrict__ bias,  // [N]
    const float* __restrict__ gamma, // [9] prev-block BN affine
    const float* __restrict__ beta,  // [9]
    float* __restrict__ hout,        // [B,9,N] raw
    float invp)
{
    constexpr int CPM  = KPM / KC;      // chunks per matrix
    constexpr int NCH  = 5 * CPM;
    constexpr int KS   = KC / 8;        // k8 steps per chunk
    constexpr int KTOT = 5 * KPM;
    constexpr int ASTR = KC + 4;
    constexpr int ASZ  = 144 * ASTR;
    constexpr int BSZ  = N * KC;
    constexpr int NT   = N / 16;        // n8 tiles per warp (half of N)

    extern __shared__ __align__(16) float sm[];
    float* h_s    = sm;                        // 144*DIN
    float* adj_s  = h_s + 144*DIN;             // 16*4*81
    float* As     = adj_s + 16*NR*81;          // 2*ASZ
    float* Bs     = As + 2*ASZ;                // 2*BSZ
    float* bias_s = Bs + 2*BSZ;                // N
    __shared__ float red[32];
    __shared__ float nrm[32];

    const int tid  = threadIdx.x, lane = tid & 31, wid = tid >> 5;
    const int mtile = wid >> 1, nhalf = wid & 1;
    const int bBase = blockIdx.x * 16;

    // B prefetch chunks 0,1 (independent of h)
    auto loadB = [&](int c, int s){
        constexpr int NV = N * KC / 4;
        #pragma unroll
        for (int i = tid; i < NV; i += TPB){
            int n8 = i / (KS*16), rem = i - n8*(KS*16);
            int ksl = rem >> 4, q = rem & 15;
            const float* src = Bp + ((size_t)n8*(KTOT/8) + c*KS + ksl)*64 + q*4;
            CPA16(s2u(Bs + s*BSZ + (n8*KS + ksl)*64 + q*4), src);
        }
        CPA_COMMIT();
    };
    loadB(0, 0);
    if (NCH > 1) loadB(1, 1);

    if (tid < 32) red[tid] = 0.f;
    if (NORM && tid < NA){
        float s = g_stats[SIN][0][tid], q = g_stats[SIN][1][tid];
        float mean = s*invp, var = q*invp - mean*mean;
        float a = rsqrtf(var + BN_EPS) * gamma[tid];
        nrm[tid] = a; nrm[16+tid] = beta[tid] - mean*a;
    }
    for (int i = tid; i < N; i += TPB) bias_s[i] = bias[i];
    __syncthreads();

    // h tile (normalized + activated if NORM) + adj tile
    for (int i = tid; i < 144*DIN; i += TPB){
        float v = hin[(size_t)bBase*NA*DIN + i];
        if (NORM){
            int n = (i / DIN) % NA;
            v = fmaf(v, nrm[n], nrm[16+n]);
            v = v > 0.f ? v : LRS*v;
        }
        h_s[i] = v;
    }
    for (int i = tid; i < 16*NR*81; i += TPB)
        adj_s[i] = adj[(size_t)bBase*NR*81 + i];
    __syncthreads();

    // produce A chunk c into buffer buf
    auto produce = [&](int c, int buf){
        if (wid >= 16) return;
        const int mat = c / CPM, k0 = (c - mat*CPM)*KC;
        const int b = wid;
        const int kk = k0 + lane;
        const bool vc = (lane < KC) && (kk < DIN);
        float* dst = As + buf*ASZ + (b*NA)*ASTR + lane;
        if (mat == 0){
            #pragma unroll
            for (int n = 0; n < NA; n++){
                float v = vc ? h_s[(b*NA + n)*DIN + kk] : 0.f;
                if (lane < KC) dst[n*ASTR] = v;
            }
        } else {
            float hv[NA];
            #pragma unroll
            for (int m = 0; m < NA; m++)
                hv[m] = vc ? h_s[(b*NA + m)*DIN + kk] : 0.f;
            const float* ar = adj_s + ((b*NR + (mat-1))*NA)*NA;
            #pragma unroll
            for (int n = 0; n < NA; n++){
                float acc = 0.f;
                #pragma unroll
                for (int m = 0; m < NA; m++) acc = fmaf(ar[n*NA + m], hv[m], acc);
                if (lane < KC) dst[n*ASTR] = acc;
            }
        }
    };

    produce(0, 0);

    float cacc[NT][4];
    #pragma unroll
    for (int j = 0; j < NT; j++)
        #pragma unroll
        for (int q = 0; q < 4; q++) cacc[j][q] = 0.f;

    const int ar0 = mtile*16 + (lane >> 2);
    const int akc = lane & 3;

    for (int c = 0; c < NCH; c++){
        const int s = c & 1;
        if (c < NCH-1) CPA_WAIT(1); else CPA_WAIT(0);
        __syncthreads();                       // As[s], Bs[s] ready
        const uint32_t* Au = (const uint32_t*)(As + s*ASZ);
        const uint32_t* Bu = (const uint32_t*)(Bs + s*BSZ);
        #pragma unroll
        for (int ks = 0; ks < KS; ks++){
            uint32_t a0, a1, a2, a3;
            int k0 = ks*8 + akc;
            a0 = Au[ar0*ASTR + k0];
            a1 = Au[(ar0+8)*ASTR + k0];
            a2 = Au[ar0*ASTR + k0 + 4];
            a3 = Au[(ar0+8)*ASTR + k0 + 4];
            #pragma unroll
            for (int j = 0; j < NT; j++){
                int n8 = nhalf*NT + j;
                uint32_t b0 = Bu[(n8*KS + ks)*64 + lane*2];
                uint32_t b1 = Bu[(n8*KS + ks)*64 + lane*2 + 1];
                mma_tf32(cacc[j][0], cacc[j][1], cacc[j][2], cacc[j][3],
                         a0, a1, a2, a3, b0, b1);
            }
        }
        if (c + 1 < NCH) produce(c + 1, s ^ 1);   // overlaps with MMA stream
        __syncthreads();                           // Bs[s]/As[s] free
        if (c + 2 < NCH) loadB(c + 2, s);
    }

    // epilogue: bias, raw store, BN stats
    #pragma unroll
    for (int half = 0; half < 2; half++){
        int r0   = mtile*16 + (lane >> 2) + half*8;
        int grow = blockIdx.x*144 + r0;
        int an   = r0 % NA;
        float ssum = 0.f, qsum = 0.f;
        float* op = &hout[(size_t)grow*N];
        #pragma unroll
        for (int j = 0; j < NT; j++){
            int col = nhalf*(N/2) + j*8 + (lane & 3)*2;
            float v0 = cacc[j][half*2+0] + bias_s[col];
            float v1 = cacc[j][half*2+1] + bias_s[col+1];
            float2 st2; st2.x = v0; st2.y = v1;
            *(float2*)(op + col) = st2;
            ssum += v0 + v1;
            qsum = fmaf(v0, v0, qsum); qsum = fmaf(v1, v1, qsum);
        }
        atomicAdd(&red[an],      ssum);
        atomicAdd(&red[16 + an], qsum);
    }
    __syncthreads();
    if (tid < NA){
        atomicAdd(&g_stats[SOUT][0][tid], red[tid]);
        atomicAdd(&g_stats[SOUT][1][tid], red[16 + tid]);
    }
}

// ---------------- readout: BN + act + masked sum + FC ----------------
__global__ void __launch_bounds__(256) readout_kernel(
    const float* __restrict__ mask, const float* __restrict__ fcw,
    const float* __restrict__ fcb,  const float* __restrict__ gamma,
    const float* __restrict__ beta, float* __restrict__ out, float inv_count)
{
    __shared__ float a_s[NA], c_s[NA], fcs[256];
    int tid = threadIdx.x;
    if (tid < NA){
        float s = g_stats[2][0][tid], q = g_stats[2][1][tid];
        float mean = s*inv_count, var = q*inv_count - mean*mean;
        float a = rsqrtf(var + BN_EPS)*gamma[tid];
        a_s[tid] = a; c_s[tid] = beta[tid] - mean*a;
    }
    fcs[tid] = fcw[tid];
    __syncthreads();
    int lane = tid & 31, w = tid >> 5;
    int b = blockIdx.x*8 + w;
    float accv = 0.f;
    #pragma unroll
    for (int n = 0; n < NA; n++){
        float mk = mask[b*NA + n];
        const float* hp = &g_h2[((size_t)b*NA + n)*256];
        float aa = a_s[n], cc = c_s[n];
        #pragma unroll
        for (int j = 0; j < 8; j++){
            int e = lane + 32*j;
            float v = fmaf(hp[e], aa, cc);
            v = v > 0.f ? v : LRS*v;
            accv = fmaf(v*mk, fcs[e], accv);
        }
    }
    #pragma unroll
    for (int o = 16; o > 0; o >>= 1) accv += __shfl_xor_sync(0xffffffffu, accv, o);
    if (lane == 0) out[b] = accv + fcb[0];
}

extern "C" void kernel_launch(void* const* d_in, const int* in_sizes, int n_in,
                              void* d_out, int out_size)
{
    const float* atom = (const float*)d_in[0];
    const float* adj  = (const float*)d_in[1];
    const float* mask = (const float*)d_in[2];
    const float* ws0=(const float*)d_in[3],  *wr0=(const float*)d_in[4],  *b0=(const float*)d_in[5],  *g0=(const float*)d_in[6],  *be0=(const float*)d_in[7];
    const float* ws1=(const float*)d_in[8],  *wr1=(const float*)d_in[9],  *b1=(const float*)d_in[10], *g1=(const float*)d_in[11], *be1=(const float*)d_in[12];
    const float* ws2=(const float*)d_in[13], *wr2=(const float*)d_in[14], *b2=(const float*)d_in[15], *g2=(const float*)d_in[16], *be2=(const float*)d_in[17];
    const float* fcw=(const float*)d_in[18], *fcb=(const float*)d_in[19];
    float* out = (float*)d_out;

    float *h0,*h1,*h2,*wtb;
    cudaGetSymbolAddress((void**)&h0, g_h0);
    cudaGetSymbolAddress((void**)&h1, g_h1);
    cudaGetSymbolAddress((void**)&h2, g_h2);
    cudaGetSymbolAddress((void**)&wtb, g_wt);

    // dynamic smem (floats): 144*DIN + 16*4*81 + 2*144*(KC+4) + 2*N*KC + N
    const int sm0 = (144*5   + 5184 + 2*144*12 + 2*64*8   + 64)  * 4;   //  ~41 KB
    const int sm1 = (144*64  + 5184 + 2*144*36 + 2*128*32 + 128) * 4;   // ~132 KB
    const int sm2 = (144*128 + 5184 + 2*144*36 + 2*256*32 + 256) * 4;   // ~202 KB
    cudaFuncSetAttribute((const void*)rgcn_fused<5,8,64,8,0,false,0>,
                         cudaFuncAttributeMaxDynamicSharedMemorySize, sm0);
    cudaFuncSetAttribute((const void*)rgcn_fused<64,64,128,32,1,true,0>,
                         cudaFuncAttributeMaxDynamicSharedMemorySize, sm1);
    cudaFuncSetAttribute((const void*)rgcn_fused<128,128,256,32,2,true,1>,
                         cudaFuncAttributeMaxDynamicSharedMemorySize, sm2);

    const int GRID = MTOT/144;   // 2048

    zero_stats_kernel<<<1,128>>>();

    // block 0: DIN=5 (KPM=8), N=64, KC=8 -> NCH=5
    wt_build<5,64,8><<<(64*40+255)/256,256>>>(ws0, wr0, wtb);
    rgcn_fused<5,8,64,8,0,false,0><<<GRID,TPB,sm0>>>(
        atom, adj, wtb, b0, g0, be0, h0, 0.f);

    // block 1: DIN=64, N=128, KC=32 -> NCH=10
    wt_build<64,128,64><<<(128*320+255)/256,256>>>(ws1, wr1, wtb);
    rgcn_fused<64,64,128,32,1,true,0><<<GRID,TPB,sm1>>>(
        h0, adj, wtb, b1, g0, be0, h1, 1.f/((float)BATCH*64.f));

    // block 2: DIN=128, N=256, KC=32 -> NCH=20
    wt_build<128,256,128><<<(256*640+255)/256,256>>>(ws2, wr2, wtb);
    rgcn_fused<128,128,256,32,2,true,1><<<GRID,TPB,sm2>>>(
        h1, adj, wtb, b2, g1, be1, h2, 1.f/((float)BATCH*128.f));

    readout_kernel<<<BATCH/8,256>>>(mask, fcw, fcb, g2, be2, out, 1.f/((float)BATCH*256.f));
}

// round 6
// speedup vs baseline: 1.2256x; 1.2256x over previous
#include <cuda_runtime.h>
#include <cstdint>
#include <math.h>

#define BATCH 32768
#define NA 9
#define NR 4
#define LRS 0.2f
#define BN_EPS 1e-5f
#define MTOT (BATCH*NA)

// ---- scratch (device globals; no allocs) ----
__device__ float g_h0[(size_t)MTOT*64];
__device__ float g_h1[(size_t)MTOT*128];
__device__ float g_h2[(size_t)MTOT*256];
__device__ float g_x [(size_t)MTOT*640];
__device__ float g_wt[256*640];
__device__ float g_stats[3][2][16];

__global__ void zero_stats_kernel() {
    int i = threadIdx.x;
    if (i < 96) ((float*)g_stats)[i] = 0.0f;
}

// ---------------- helpers ----------------
static __device__ __forceinline__ uint32_t s2u(const void* p){
    uint32_t a;
    asm("{ .reg .u64 t; cvta.to.shared.u64 t, %1; cvt.u32.u64 %0, t; }":"=r"(a):"l"(p));
    return a;
}
static __device__ __forceinline__ float tf32r(float v){
    uint32_t u; asm("cvt.rna.tf32.f32 %0, %1;" : "=r"(u) : "f"(v));
    return __uint_as_float(u);
}
#define CPA16(dst,src) asm volatile("cp.async.cg.shared.global [%0], [%1], 16;"::"r"(dst),"l"(src):"memory")
#define CPA_COMMIT()   asm volatile("cp.async.commit_group;":::"memory")
#define CPA_WAIT(n)    asm volatile("cp.async.wait_group %0;"::"n"(n):"memory")

static __device__ __forceinline__ void mma_tf32(
    float& d0, float& d1, float& d2, float& d3,
    uint32_t a0, uint32_t a1, uint32_t a2, uint32_t a3,
    uint32_t b0, uint32_t b1)
{
    asm volatile(
        "mma.sync.aligned.m16n8k8.row.col.f32.tf32.tf32.f32 "
        "{%0,%1,%2,%3}, {%4,%5,%6,%7}, {%8,%9}, {%0,%1,%2,%3};"
        : "+f"(d0), "+f"(d1), "+f"(d2), "+f"(d3)
        : "r"(a0), "r"(a1), "r"(a2), "r"(a3), "r"(b0), "r"(b1));
}

// ---------------- Wt build: frag-packed, tf32-rounded ----------------
template<int DIN,int DOUT,int K5P>
__global__ void wt_build(const float* __restrict__ ws, const float* __restrict__ wr,
                         float* __restrict__ bp){
    int i = blockIdx.x*256 + threadIdx.x;
    if (i >= DOUT*K5P) return;
    int n = i / K5P, k = i - n*K5P;
    float v = 0.f;
    if (k < DIN) v = ws[k*DOUT + n];
    else if (k < 5*DIN) {
        int r = (k - DIN) / DIN, kk = (k - DIN) - r*DIN;
        v = wr[(size_t)(r*DIN + kk)*DOUT + n];
    }
    int kstep = k >> 3, kk = k & 7;
    int lane = (n & 7)*4 + (kk & 3), half = kk >> 2;
    bp[((size_t)(n >> 3)*(K5P/8) + kstep)*64 + lane*2 + half] = tf32r(v);
}

// ---------------- X build: X = [h_norm | adj_r @ h_norm], tf32-rounded ----------------
template<int DIN, int K5P, bool NORM, int SIN>
__global__ void __launch_bounds__(256) x_build(
    const float* __restrict__ hin, const float* __restrict__ adj,
    const float* __restrict__ gamma, const float* __restrict__ beta,
    float* __restrict__ Xo, float invp)
{
    constexpr int MB = 8;
    __shared__ float h_s[MB*NA*DIN];
    __shared__ float adj_s[MB*NR*NA*NA];
    __shared__ float nrm[32];
    const int tid = threadIdx.x;
    const size_t mb = (size_t)blockIdx.x * MB;
    if (NORM && tid < NA){
        float s = g_stats[SIN][0][tid], q = g_stats[SIN][1][tid];
        float mean = s*invp, var = q*invp - mean*mean;
        float a = rsqrtf(var + BN_EPS) * gamma[tid];
        nrm[tid] = a; nrm[16+tid] = beta[tid] - mean*a;
    }
    __syncthreads();
    for (int i = tid; i < MB*NA*DIN; i += 256){
        float v = hin[mb*NA*DIN + i];
        if (NORM){
            int n = (i/DIN) % NA;
            v = fmaf(v, nrm[n], nrm[16+n]);
            v = v > 0.f ? v : LRS*v;
        }
        h_s[i] = v;
    }
    for (int i = tid; i < MB*NR*NA*NA; i += 256)
        adj_s[i] = adj[mb*NR*NA*NA + i];
    __syncthreads();
    for (int i = tid; i < MB*NA*K5P; i += 256){
        int row = i / K5P, col = i - row*K5P;
        int m = row / NA, n = row - m*NA;
        float v = 0.f;
        if (col < DIN) v = h_s[row*DIN + col];
        else if (col < 5*DIN){
            int r = (col - DIN) / DIN, d = (col - DIN) - r*DIN;
            const float* ar = &adj_s[((m*NR + r)*NA + n)*NA];
            const float* hc = &h_s[m*NA*DIN + d];
            #pragma unroll
            for (int mm = 0; mm < NA; mm++) v = fmaf(ar[mm], hc[mm*DIN], v);
        }
        Xo[mb*NA*K5P + i] = tf32r(v);
    }
}

// ---------------- tf32 mma.sync GEMM: hout = X @ Wt^T + bias (+BN stats) ----------------
// CTA: MROWS x N. 8 warps = 4(M) x 2(N). Warp: (MROWS/4) x N/2. 64 accum regs max.
template<int N, int NCH, int K5P, int MROWS, int SOUT, int MINCTA>
__global__ void __launch_bounds__(256, MINCTA) gemm_mma(
    const float* __restrict__ X,     // [M,K5P] tf32
    const float* __restrict__ Bp,    // frag-packed weights
    const float* __restrict__ bias,
    float* __restrict__ hout)
{
    constexpr int MT_W = MROWS/64;   // mtiles(16) per warp (WM=4)
    constexpr int NT   = N/16;       // n8 tiles per warp (WN=2)
    constexpr int ASZ  = MROWS*36;   // floats per A stage (pad 36)
    constexpr int BSZ  = N*32;       // floats per B stage
    constexpr int SSTG = (NCH > 1) ? 2 : 1;
    extern __shared__ __align__(16) float sm[];
    float* As = sm;                  // [SSTG][ASZ]
    float* Bs = sm + SSTG*ASZ;       // [SSTG][BSZ]
    __shared__ float red[32];
    __shared__ float bias_s[N];

    const int tid = threadIdx.x, lane = tid & 31, wid = tid >> 5;
    const int warp_n = wid & 1, warp_m = wid >> 1;
    const int mBase = blockIdx.x * MROWS;

    if (tid < 32) red[tid] = 0.f;
    for (int i = tid; i < N; i += 256) bias_s[i] = bias[i];

    auto loadA = [&](int kc, int s){
        const float* src = X + (size_t)mBase*K5P + kc*32;
        #pragma unroll
        for (int i = tid; i < MROWS*8; i += 256){
            int row = i >> 3, seg = i & 7;
            CPA16(s2u(As + s*ASZ + row*36 + seg*4), src + (size_t)row*K5P + seg*4);
        }
    };
    auto loadB = [&](int kc, int s){
        #pragma unroll
        for (int i = tid; i < N*8; i += 256){
            int n8 = i >> 6, rem = i & 63, ks = rem >> 4, q = rem & 15;
            const float* src = Bp + ((size_t)n8*(K5P/8) + kc*4 + ks)*64 + q*4;
            CPA16(s2u(Bs + s*BSZ + (n8*4 + ks)*64 + q*4), src);
        }
    };

    loadA(0,0); loadB(0,0); CPA_COMMIT();
    if (NCH > 1){ loadA(1,1); loadB(1,1); CPA_COMMIT(); }

    float cacc[MT_W][NT][4];
    #pragma unroll
    for (int mtw=0; mtw<MT_W; mtw++)
        #pragma unroll
        for (int j=0;j<NT;j++)
            #pragma unroll
            for (int q=0;q<4;q++) cacc[mtw][j][q] = 0.f;

    for (int kc = 0; kc < NCH; kc++){
        const int s = kc & 1;
        if (kc < NCH-1) CPA_WAIT(1); else CPA_WAIT(0);
        __syncthreads();
        const uint32_t* Au = (const uint32_t*)(As + s*ASZ);
        const uint2*    Bu = (const uint2*)   (Bs + s*BSZ);
        #pragma unroll
        for (int ks = 0; ks < 4; ks++){
            uint32_t a[MT_W][4];
            #pragma unroll
            for (int mtw = 0; mtw < MT_W; mtw++){
                int r0 = (warp_m*MT_W + mtw)*16 + (lane >> 2);
                int k0 = ks*8 + (lane & 3);
                a[mtw][0] = Au[r0*36 + k0];
                a[mtw][1] = Au[(r0+8)*36 + k0];
                a[mtw][2] = Au[r0*36 + k0 + 4];
                a[mtw][3] = Au[(r0+8)*36 + k0 + 4];
            }
            #pragma unroll
            for (int j = 0; j < NT; j++){
                int n8 = warp_n*NT + j;
                uint2 bv = Bu[(n8*4 + ks)*32 + lane];
                #pragma unroll
                for (int mtw = 0; mtw < MT_W; mtw++)
                    mma_tf32(cacc[mtw][j][0], cacc[mtw][j][1],
                             cacc[mtw][j][2], cacc[mtw][j][3],
                             a[mtw][0], a[mtw][1], a[mtw][2], a[mtw][3],
                             bv.x, bv.y);
            }
        }
        __syncthreads();
        if (kc + 2 < NCH){ loadA(kc+2, s); loadB(kc+2, s); CPA_COMMIT(); }
    }

    // epilogue: bias, raw store, BN stats
    #pragma unroll
    for (int mtw = 0; mtw < MT_W; mtw++){
        #pragma unroll
        for (int half = 0; half < 2; half++){
            int r0   = (warp_m*MT_W + mtw)*16 + (lane >> 2) + half*8;
            int grow = mBase + r0;
            int an   = grow % NA;
            float ssum = 0.f, qsum = 0.f;
            float* op = &hout[(size_t)grow*N];
            #pragma unroll
            for (int j = 0; j < NT; j++){
                int col = warp_n*(N/2) + j*8 + (lane & 3)*2;
                float v0 = cacc[mtw][j][half*2+0] + bias_s[col];
                float v1 = cacc[mtw][j][half*2+1] + bias_s[col+1];
                float2 st2; st2.x = v0; st2.y = v1;
                *(float2*)(op + col) = st2;
                ssum += v0 + v1;
                qsum = fmaf(v0, v0, qsum); qsum = fmaf(v1, v1, qsum);
            }
            atomicAdd(&red[an],      ssum);
            atomicAdd(&red[16 + an], qsum);
        }
    }
    __syncthreads();
    if (tid < NA){
        atomicAdd(&g_stats[SOUT][0][tid], red[tid]);
        atomicAdd(&g_stats[SOUT][1][tid], red[16 + tid]);
    }
}

// ---------------- readout: BN + act + masked sum + FC ----------------
__global__ void __launch_bounds__(256) readout_kernel(
    const float* __restrict__ mask, const float* __restrict__ fcw,
    const float* __restrict__ fcb,  const float* __restrict__ gamma,
    const float* __restrict__ beta, float* __restrict__ out, float inv_count)
{
    __shared__ float a_s[NA], c_s[NA], fcs[256];
    int tid = threadIdx.x;
    if (tid < NA){
        float s = g_stats[2][0][tid], q = g_stats[2][1][tid];
        float mean = s*inv_count, var = q*inv_count - mean*mean;
        float a = rsqrtf(var + BN_EPS)*gamma[tid];
        a_s[tid] = a; c_s[tid] = beta[tid] - mean*a;
    }
    fcs[tid] = fcw[tid];
    __syncthreads();
    int lane = tid & 31, w = tid >> 5;
    int b = blockIdx.x*8 + w;
    float accv = 0.f;
    #pragma unroll
    for (int n = 0; n < NA; n++){
        float mk = mask[b*NA + n];
        const float* hp = &g_h2[((size_t)b*NA + n)*256];
        float aa = a_s[n], cc = c_s[n];
        #pragma unroll
        for (int j = 0; j < 8; j++){
            int e = lane + 32*j;
            float v = fmaf(hp[e], aa, cc);
            v = v > 0.f ? v : LRS*v;
            accv = fmaf(v*mk, fcs[e], accv);
        }
    }
    #pragma unroll
    for (int o = 16; o > 0; o >>= 1) accv += __shfl_xor_sync(0xffffffffu, accv, o);
    if (lane == 0) out[b] = accv + fcb[0];
}

extern "C" void kernel_launch(void* const* d_in, const int* in_sizes, int n_in,
                              void* d_out, int out_size)
{
    const float* atom = (const float*)d_in[0];
    const float* adj  = (const float*)d_in[1];
    const float* mask = (const float*)d_in[2];
    const float* ws0=(const float*)d_in[3],  *wr0=(const float*)d_in[4],  *b0=(const float*)d_in[5],  *g0=(const float*)d_in[6],  *be0=(const float*)d_in[7];
    const float* ws1=(const float*)d_in[8],  *wr1=(const float*)d_in[9],  *b1=(const float*)d_in[10], *g1=(const float*)d_in[11], *be1=(const float*)d_in[12];
    const float* ws2=(const float*)d_in[13], *wr2=(const float*)d_in[14], *b2=(const float*)d_in[15], *g2=(const float*)d_in[16], *be2=(const float*)d_in[17];
    const float* fcw=(const float*)d_in[18], *fcb=(const float*)d_in[19];
    float* out = (float*)d_out;

    float *h0,*h1,*h2,*xb,*wtb;
    cudaGetSymbolAddress((void**)&h0, g_h0);
    cudaGetSymbolAddress((void**)&h1, g_h1);
    cudaGetSymbolAddress((void**)&h2, g_h2);
    cudaGetSymbolAddress((void**)&xb, g_x);
    cudaGetSymbolAddress((void**)&wtb, g_wt);

    // dynamic smem: (SSTG*MROWS*36 + SSTG*N*32) * 4 bytes
    const int sm0 = (1*128*36 + 1*64*32)  * 4;   // 26624
    const int sm1 = (2*128*36 + 2*128*32) * 4;   // 69632
    const int sm2 = (2*64*36  + 2*256*32) * 4;   // 83968
    cudaFuncSetAttribute((const void*)gemm_mma<64,1,32,128,0,3>,
                         cudaFuncAttributeMaxDynamicSharedMemorySize, sm0);
    cudaFuncSetAttribute((const void*)gemm_mma<128,10,320,128,1,2>,
                         cudaFuncAttributeMaxDynamicSharedMemorySize, sm1);
    cudaFuncSetAttribute((const void*)gemm_mma<256,20,640,64,2,2>,
                         cudaFuncAttributeMaxDynamicSharedMemorySize, sm2);

    zero_stats_kernel<<<1,128>>>();

    // block 0: DIN=5, K5P=32, DOUT=64
    wt_build<5,64,32><<<(64*32+255)/256,256>>>(ws0, wr0, wtb);
    x_build<5,32,false,0><<<BATCH/8,256>>>(atom, adj, g0, be0, xb, 0.f);
    gemm_mma<64,1,32,128,0,3><<<MTOT/128,256,sm0>>>(xb, wtb, b0, h0);

    // block 1: DIN=64, K5P=320, DOUT=128
    wt_build<64,128,320><<<(128*320+255)/256,256>>>(ws1, wr1, wtb);
    x_build<64,320,true,0><<<BATCH/8,256>>>(h0, adj, g0, be0, xb, 1.f/((float)BATCH*64.f));
    gemm_mma<128,10,320,128,1,2><<<MTOT/128,256,sm1>>>(xb, wtb, b1, h1);

    // block 2: DIN=128, K5P=640, DOUT=256
    wt_build<128,256,640><<<(256*640+255)/256,256>>>(ws2, wr2, wtb);
    x_build<128,640,true,1><<<BATCH/8,256>>>(h1, adj, g1, be1, xb, 1.f/((float)BATCH*128.f));
    gemm_mma<256,20,640,64,2,2><<<MTOT/64,256,sm2>>>(xb, wtb, b2, h2);

    readout_kernel<<<BATCH/8,256>>>(mask, fcw, fcb, g2, be2, out, 1.f/((float)BATCH*256.f));
}